// round 2
// baseline (speedup 1.0000x reference)
#include <cuda_runtime.h>
#include <math.h>

#define N_ATOMS 8000
#define N_PAIRS 80000
#define NF      32
#define N_DIST  16
#define SBLK    (N_DIST * NF)      // 512 per-atom M entries
#define GN_EPS  1e-5f
#define HARD_CUTOFF 6.5f
#define CUT_K   0.24166097335f     // (pi/2)/6.5

// Scratch (no allocations allowed): M[j][d][o] and segment offsets.
__device__ float g_M[(size_t)N_ATOMS * SBLK];   // 16 MB, L2-resident
__device__ int   g_off[N_ATOMS + 1];

// ---------------------------------------------------------------------------
// Kernel 0: segment offsets from sorted pair_first.
// off[a] = first p with pair_first[p] >= a.
// ---------------------------------------------------------------------------
__global__ void k_offsets(const int* __restrict__ pf) {
    int p = blockIdx.x * blockDim.x + threadIdx.x;
    if (p >= N_PAIRS) return;
    int a = pf[p];
    if (p == 0) {
        for (int x = 0; x <= a; ++x) g_off[x] = 0;
    }
    int an = (p + 1 < N_PAIRS) ? pf[p + 1] : N_ATOMS;
    for (int x = a + 1; x <= an; ++x) g_off[x] = p + 1;
}

// ---------------------------------------------------------------------------
// Kernel 1: M[j][d][o] = sum_f int_weights[d][o][f] * feat[j][f]
// int_weights flat index (d*32+o)*32+f == e*32+f.
// One block per atom, 128 threads, 4 outputs each.
// ---------------------------------------------------------------------------
__global__ __launch_bounds__(128) void k_precompute(const float* __restrict__ feat,
                                                    const float* __restrict__ W) {
    __shared__ float sf[NF];
    int a = blockIdx.x;
    int t = threadIdx.x;
    if (t < NF) sf[t] = feat[a * NF + t];
    __syncthreads();
    float* Mrow = g_M + (size_t)a * SBLK;
    #pragma unroll
    for (int e = t; e < SBLK; e += 128) {
        const float* w = W + e * NF;
        float acc = 0.f;
        #pragma unroll
        for (int f = 0; f < NF; ++f) acc += sf[f] * w[f];
        Mrow[e] = acc;
    }
}

// ---------------------------------------------------------------------------
// Kernel 2: per-atom pair accumulation + invariants + GroupNorm + mixing +
//           self-interaction.  One block (128 thr = 4 warps) per atom.
// ---------------------------------------------------------------------------
__global__ __launch_bounds__(128) void k_main(
    const float* __restrict__ feat,
    const float* __restrict__ rhat,
    const float* __restrict__ dist,
    const float* __restrict__ sw,     // selfint_w (32,32)
    const float* __restrict__ sb,     // selfint_b (32,)
    const float* __restrict__ mw,     // mixing_weights (32,2,32) flat
    const float* __restrict__ gw,     // gn_weight (64,)
    const float* __restrict__ gb,     // gn_bias (64,)
    const float* __restrict__ mu,     // sens_mu (16,)
    const float* __restrict__ sigma,  // sens_sigma (16,)
    const int*   __restrict__ psec,   // pair_second
    float*       __restrict__ out)
{
    const int a    = blockIdx.x;
    const int t    = threadIdx.x;
    const int wid  = t >> 5;
    const int lane = t & 31;

    __shared__ float part[4][4][NF];   // [warp][comp][o]
    __shared__ float tf[4][NF];        // [comp][o]
    __shared__ float xn[2][NF];        // normalized invariants

    const int p0 = g_off[a];
    const int p1 = g_off[a + 1];

    const float mymu = (lane < N_DIST) ? mu[lane]    : 0.f;
    const float mysg = (lane < N_DIST) ? sigma[lane] : 1.f;

    float acc0 = 0.f, acc1 = 0.f, acc2 = 0.f, acc3 = 0.f;

    for (int p = p0 + wid; p < p1; p += 4) {
        const int   j = psec[p];
        const float d = dist[p];

        float cut = 0.f;
        if (d < HARD_CUTOFF) {
            float c = __cosf(d * CUT_K);
            cut = c * c;
        }
        float s = 0.f;
        if (lane < N_DIST) {
            float z = (1.f / d - mymu) / mysg;
            s = __expf(-0.5f * z * z) * cut;
        }
        float r = (lane < 4) ? rhat[p * 4 + lane] : 0.f;

        const float* Mrow = g_M + (size_t)j * SBLK;
        float y = 0.f;
        #pragma unroll
        for (int dd = 0; dd < N_DIST; ++dd)
            y += __shfl_sync(0xffffffffu, s, dd) * Mrow[dd * NF + lane];

        acc0 += __shfl_sync(0xffffffffu, r, 0) * y;
        acc1 += __shfl_sync(0xffffffffu, r, 1) * y;
        acc2 += __shfl_sync(0xffffffffu, r, 2) * y;
        acc3 += __shfl_sync(0xffffffffu, r, 3) * y;
    }

    part[wid][0][lane] = acc0;
    part[wid][1][lane] = acc1;
    part[wid][2][lane] = acc2;
    part[wid][3][lane] = acc3;
    __syncthreads();

    // cross-warp reduce: thread (c=wid, o=lane)
    tf[wid][lane] = part[0][wid][lane] + part[1][wid][lane]
                  + part[2][wid][lane] + part[3][wid][lane];
    __syncthreads();

    // Invariants + GroupNorm (group g stats over its 32 channels)
    if (wid < 2) {
        float x;
        if (wid == 0) {
            x = tf[0][lane];
        } else {
            float a1 = tf[1][lane], a2 = tf[2][lane], a3 = tf[3][lane];
            x = a1 * a1 + a2 * a2 + a3 * a3;
        }
        float sum = x, sq = x * x;
        #pragma unroll
        for (int o = 16; o; o >>= 1) {
            sum += __shfl_xor_sync(0xffffffffu, sum, o);
            sq  += __shfl_xor_sync(0xffffffffu, sq,  o);
        }
        float mean = sum * (1.f / 32.f);
        float var  = sq  * (1.f / 32.f) - mean * mean;
        float inv  = rsqrtf(var + GN_EPS);
        xn[wid][lane] = (x - mean) * inv * gw[wid * NF + lane] + gb[wid * NF + lane];
    }
    __syncthreads();

    // Mixing matvec + self interaction, warp 0, lane = output channel
    if (wid == 0) {
        float selfp = sb[lane];
        const float* fr = feat + a * NF;
        #pragma unroll
        for (int f = 0; f < NF; ++f)
            selfp += fr[f] * sw[lane * NF + f];

        float mx = 0.f;
        #pragma unroll
        for (int o = 0; o < NF; ++o) {
            mx += xn[0][o] * mw[(o * 2 + 0) * NF + lane];
            mx += xn[1][o] * mw[(o * 2 + 1) * NF + lane];
        }
        out[a * NF + lane] = mx + selfp;
    }
}

// ---------------------------------------------------------------------------
// Launch. Inputs in setup_inputs order:
// 0 in_features 1 tensor_rhats 2 dist_pairs 3 int_weights 4 selfint_w
// 5 selfint_b 6 mixing_weights 7 gn_weight 8 gn_bias 9 sens_mu 10 sens_sigma
// 11 pair_first 12 pair_second
// ---------------------------------------------------------------------------
extern "C" void kernel_launch(void* const* d_in, const int* in_sizes, int n_in,
                              void* d_out, int out_size) {
    const float* in_features = (const float*)d_in[0];
    const float* tensor_rhats= (const float*)d_in[1];
    const float* dist_pairs  = (const float*)d_in[2];
    const float* int_weights = (const float*)d_in[3];
    const float* selfint_w   = (const float*)d_in[4];
    const float* selfint_b   = (const float*)d_in[5];
    const float* mixing_w    = (const float*)d_in[6];
    const float* gn_weight   = (const float*)d_in[7];
    const float* gn_bias     = (const float*)d_in[8];
    const float* sens_mu     = (const float*)d_in[9];
    const float* sens_sigma  = (const float*)d_in[10];
    const int*   pair_first  = (const int*)d_in[11];
    const int*   pair_second = (const int*)d_in[12];
    float* out = (float*)d_out;

    k_offsets<<<(N_PAIRS + 255) / 256, 256>>>(pair_first);
    k_precompute<<<N_ATOMS, 128>>>(in_features, int_weights);
    k_main<<<N_ATOMS, 128>>>(in_features, tensor_rhats, dist_pairs,
                             selfint_w, selfint_b, mixing_w,
                             gn_weight, gn_bias, sens_mu, sens_sigma,
                             pair_second, out);
}

// round 6
// speedup vs baseline: 10.1444x; 10.1444x over previous
#include <cuda_runtime.h>
#include <math.h>

#define N_ATOMS 8000
#define N_PAIRS 80000
#define NF      32
#define N_DIST  16
#define SBLK    (N_DIST * NF)      // 512 per-atom M entries
#define GN_EPS  1e-5f
#define HARD_CUTOFF 6.5f
#define CUT_K   0.24166097335f     // (pi/2)/6.5
#define ATILE   32
#define EHALF   256

// Scratch (no allocations allowed): M[j][d][o] and segment offsets.
__device__ float g_M[(size_t)N_ATOMS * SBLK];   // 16 MB, L2-resident
__device__ int   g_off[N_ATOMS + 1];

// ---------------------------------------------------------------------------
// Kernel 0: segment offsets from sorted pair_first.
// ---------------------------------------------------------------------------
__global__ void k_offsets(const int* __restrict__ pf) {
    int p = blockIdx.x * blockDim.x + threadIdx.x;
    if (p >= N_PAIRS) return;
    int a = pf[p];
    if (p == 0) {
        for (int x = 0; x <= a; ++x) g_off[x] = 0;
    }
    int an = (p + 1 < N_PAIRS) ? pf[p + 1] : N_ATOMS;
    for (int x = a + 1; x <= an; ++x) g_off[x] = p + 1;
}

// ---------------------------------------------------------------------------
// Kernel 1: tiled GEMM  M[a][e] = sum_f W[e][f] * feat[a][f]   (coalesced)
// grid = (2 e-halves, 250 atom tiles), 256 threads.
// Also writes self-interaction part into `out` (eh==0 blocks).
// ---------------------------------------------------------------------------
__global__ __launch_bounds__(256) void k_precompute(
    const float* __restrict__ feat, const float* __restrict__ W,
    const float* __restrict__ sw,   const float* __restrict__ sb,
    float* __restrict__ out)
{
    __shared__ float sW[EHALF][NF + 1];   // padded: conflict-free reg load
    __shared__ float sF[ATILE][NF];
    __shared__ float sT[NF][NF + 1];      // selfint_w transposed (eh==0 only)

    const int t      = threadIdx.x;
    const int eh     = blockIdx.x;            // 0 or 1
    const int a0     = blockIdx.y * ATILE;
    const int e_base = eh * EHALF;

    for (int i = t; i < EHALF * NF; i += 256)
        sW[i >> 5][i & 31] = W[e_base * NF + i];           // coalesced
    for (int i = t; i < ATILE * NF; i += 256)
        sF[i >> 5][i & 31] = feat[a0 * NF + i];            // coalesced
    if (eh == 0) {
        for (int i = t; i < NF * NF; i += 256)
            sT[i & 31][i >> 5] = sw[i];                    // coalesced, pad ok
    }
    __syncthreads();

    float w[NF];
    #pragma unroll
    for (int f = 0; f < NF; ++f) w[f] = sW[t][f];          // conflict-free

    #pragma unroll 4
    for (int a = 0; a < ATILE; ++a) {
        float acc = 0.f;
        #pragma unroll
        for (int f = 0; f < NF; ++f) acc += w[f] * sF[a][f];   // broadcast LDS
        g_M[(size_t)(a0 + a) * SBLK + e_base + t] = acc;       // coalesced
    }

    if (eh == 0) {
        const int o = t & 31;
        for (int a = t >> 5; a < ATILE; a += 8) {
            float acc = sb[o];
            #pragma unroll
            for (int f = 0; f < NF; ++f) acc += sF[a][f] * sT[f][o];
            out[(a0 + a) * NF + o] = acc;                      // coalesced
        }
    }
}

// ---------------------------------------------------------------------------
// Kernel 2: per-atom pair accumulation + invariants + GroupNorm + mixing.
// One block (4 warps) per atom. out already holds self-interaction part.
// ---------------------------------------------------------------------------
__global__ __launch_bounds__(128) void k_main(
    const float* __restrict__ rhat,
    const float* __restrict__ dist,
    const float* __restrict__ mw,     // mixing_weights (32,2,32) flat
    const float* __restrict__ gw,     // gn_weight (64,)
    const float* __restrict__ gb,     // gn_bias (64,)
    const float* __restrict__ mu,     // sens_mu (16,)
    const float* __restrict__ sigma,  // sens_sigma (16,)
    const int*   __restrict__ psec,   // pair_second
    float*       __restrict__ out)
{
    const int a    = blockIdx.x;
    const int t    = threadIdx.x;
    const int wid  = t >> 5;
    const int lane = t & 31;

    __shared__ float part[4][4][NF];   // [warp][comp][o]
    __shared__ float tf[4][NF];        // [comp][o]
    __shared__ float xn[2][NF];        // normalized invariants

    const int p0 = g_off[a];
    const int p1 = g_off[a + 1];

    const float mymu = (lane < N_DIST) ? mu[lane]    : 0.f;
    const float mysg = (lane < N_DIST) ? sigma[lane] : 1.f;

    float acc0 = 0.f, acc1 = 0.f, acc2 = 0.f, acc3 = 0.f;

    for (int p = p0 + wid; p < p1; p += 4) {
        const int   j = psec[p];
        const float d = dist[p];

        float cut = 0.f;
        if (d < HARD_CUTOFF) {
            float c = __cosf(d * CUT_K);
            cut = c * c;
        }
        float s = 0.f;
        if (lane < N_DIST) {
            float z = (1.f / d - mymu) / mysg;
            s = __expf(-0.5f * z * z) * cut;
        }
        float r = (lane < 4) ? rhat[p * 4 + lane] : 0.f;

        const float* Mrow = g_M + (size_t)j * SBLK;
        float y = 0.f;
        #pragma unroll
        for (int dd = 0; dd < N_DIST; ++dd)
            y += __shfl_sync(0xffffffffu, s, dd) * Mrow[dd * NF + lane];

        acc0 += __shfl_sync(0xffffffffu, r, 0) * y;
        acc1 += __shfl_sync(0xffffffffu, r, 1) * y;
        acc2 += __shfl_sync(0xffffffffu, r, 2) * y;
        acc3 += __shfl_sync(0xffffffffu, r, 3) * y;
    }

    part[wid][0][lane] = acc0;
    part[wid][1][lane] = acc1;
    part[wid][2][lane] = acc2;
    part[wid][3][lane] = acc3;
    __syncthreads();

    tf[wid][lane] = part[0][wid][lane] + part[1][wid][lane]
                  + part[2][wid][lane] + part[3][wid][lane];
    __syncthreads();

    // Invariants + GroupNorm
    if (wid < 2) {
        float x;
        if (wid == 0) {
            x = tf[0][lane];
        } else {
            float a1 = tf[1][lane], a2 = tf[2][lane], a3 = tf[3][lane];
            x = a1 * a1 + a2 * a2 + a3 * a3;
        }
        float sum = x, sq = x * x;
        #pragma unroll
        for (int o = 16; o; o >>= 1) {
            sum += __shfl_xor_sync(0xffffffffu, sum, o);
            sq  += __shfl_xor_sync(0xffffffffu, sq,  o);
        }
        float mean = sum * (1.f / 32.f);
        float var  = sq  * (1.f / 32.f) - mean * mean;
        float inv  = rsqrtf(var + GN_EPS);
        xn[wid][lane] = (x - mean) * inv * gw[wid * NF + lane] + gb[wid * NF + lane];
    }
    __syncthreads();

    // Mixing matvec; self part already resides in out[]
    if (wid == 0) {
        float mx = 0.f;
        #pragma unroll
        for (int o = 0; o < NF; ++o) {
            mx += xn[0][o] * mw[(o * 2 + 0) * NF + lane];
            mx += xn[1][o] * mw[(o * 2 + 1) * NF + lane];
        }
        out[a * NF + lane] = mx + out[a * NF + lane];
    }
}

// ---------------------------------------------------------------------------
extern "C" void kernel_launch(void* const* d_in, const int* in_sizes, int n_in,
                              void* d_out, int out_size) {
    const float* in_features = (const float*)d_in[0];
    const float* tensor_rhats= (const float*)d_in[1];
    const float* dist_pairs  = (const float*)d_in[2];
    const float* int_weights = (const float*)d_in[3];
    const float* selfint_w   = (const float*)d_in[4];
    const float* selfint_b   = (const float*)d_in[5];
    const float* mixing_w    = (const float*)d_in[6];
    const float* gn_weight   = (const float*)d_in[7];
    const float* gn_bias     = (const float*)d_in[8];
    const float* sens_mu     = (const float*)d_in[9];
    const float* sens_sigma  = (const float*)d_in[10];
    const int*   pair_first  = (const int*)d_in[11];
    const int*   pair_second = (const int*)d_in[12];
    float* out = (float*)d_out;

    k_offsets<<<(N_PAIRS + 255) / 256, 256>>>(pair_first);

    dim3 pgrid(2, N_ATOMS / ATILE);
    k_precompute<<<pgrid, 256>>>(in_features, int_weights,
                                 selfint_w, selfint_b, out);

    k_main<<<N_ATOMS, 128>>>(tensor_rhats, dist_pairs, mixing_w,
                             gn_weight, gn_bias, sens_mu, sens_sigma,
                             pair_second, out);
}